// round 13
// baseline (speedup 1.0000x reference)
#include <cuda_runtime.h>
#include <cuda_bf16.h>
#include <mma.h>
#include <math.h>
#include <cstdint>

using namespace nvcuda;

// Problem constants (fixed by the dataset)
#define BATCH 8
#define SEQ   2048
#define HDIM  4096
#define DDIM  128
#define NSENT 128

// split-K for the HMMA GEMM
#define KS2   16
#define KSL   (HDIM / KS2)     // 256 fp32 k per CTA
#define STG   64               // k per pipeline stage
#define NSTG  (KSL / STG)      // 4 stages
#define MMA_THREADS 256        // 8 warps; CTA tile M=64 x N=128
#define MROWS 64               // sentence rows per CTA (M-split x2)

// split-K for the q/v GEMVs
#define QSPL  8
#define QSEG  (HDIM / QSPL)    // 512 floats per warp segment

#define TSTRIDE 72                     // bf16 tile row stride (144B)
#define ATILE   (MROWS * TSTRIDE * 2)  // 9216 bytes per A bf16 tile (64 rows)
#define ASTAGE  (2 * ATILE)            // hi+lo = 18432
#define WTILE   (128 * TSTRIDE * 2)    // 18432 bytes per W bf16 tile (128 rows)
#define RAWA_SZ (MROWS * STG * 4)      // 16384 bytes raw fp32 A stage
#define AT_OFF  (2 * RAWA_SZ)          // 32768
#define WT_OFF  (AT_OFF + 2 * ASTAGE)  // 69632 (W single-buffered: hi, lo)
#define MMA_SMEM_TOTAL (WT_OFF + 2 * WTILE)   // 106496 bytes -> 2 CTAs/SM

// ---------------- scratch (no allocations allowed) ----------------
__device__ int   g_idx[BATCH * NSENT];
__device__ float g_qpart[QSPL * BATCH * DDIM];               // 32 KB
__device__ float g_vpart[QSPL * BATCH * NSENT];              // 32 KB
__device__ float g_part[(size_t)KS2 * BATCH * NSENT * DDIM]; // 8 MB fp32 partials
__device__ float g_kf [(size_t)BATCH * NSENT * DDIM];        // 512 KB (RoPE'd K)
__device__ __nv_bfloat16 g_Whi[(size_t)DDIM * HDIM];         // 1 MB
__device__ __nv_bfloat16 g_Wlo[(size_t)DDIM * HDIM];         // 1 MB

// ---------------- PTX helpers (baseline compute_103 only!) ----------------
__device__ __forceinline__ uint32_t smem_u32(const void* p) {
    uint32_t a;
    asm("{ .reg .u64 t; cvta.to.shared.u64 t, %1; cvt.u32.u64 %0, t; }" : "=r"(a) : "l"(p));
    return a;
}
__device__ __forceinline__ void cp_async16(uint32_t saddr, const void* g) {
    asm volatile("cp.async.cg.shared.global [%0], [%1], 16;" :: "r"(saddr), "l"(g));
}
#define CP_COMMIT() asm volatile("cp.async.commit_group;" ::: "memory")
#define CP_WAIT(n)  asm volatile("cp.async.wait_group %0;" :: "n"(n) : "memory")

// ---------------- kernel 0: pre-split Wk into hi/lo bf16 ----------------
__global__ __launch_bounds__(256) void prepw_kernel(const float* __restrict__ Wk) {
    int i = blockIdx.x * 256 + threadIdx.x;       // over DDIM*HDIM/4 = 131072 float4
    if (i >= DDIM * HDIM / 4) return;
    float4 x = ((const float4*)Wk)[i];
    __nv_bfloat162 h0 = __floats2bfloat162_rn(x.x, x.y);
    __nv_bfloat162 h1 = __floats2bfloat162_rn(x.z, x.w);
    __nv_bfloat162 l0 = __floats2bfloat162_rn(x.x - __bfloat162float(h0.x),
                                              x.y - __bfloat162float(h0.y));
    __nv_bfloat162 l1 = __floats2bfloat162_rn(x.z - __bfloat162float(h1.x),
                                              x.w - __bfloat162float(h1.y));
    uint2 hv; hv.x = *(uint32_t*)&h0; hv.y = *(uint32_t*)&h1;
    uint2 lv; lv.x = *(uint32_t*)&l0; lv.y = *(uint32_t*)&l1;
    ((uint2*)g_Whi)[i] = hv;
    ((uint2*)g_Wlo)[i] = lv;
}

// ---------------- kernel 1: extract sentence positions (MLP-64) --------
__global__ void idx_kernel(const int* __restrict__ mask) {
    int b = blockIdx.x;
    int lane = threadIdx.x;            // 32 threads
    const int4* row = (const int4*)(mask + (size_t)b * SEQ);
    int4 v[16];
#pragma unroll
    for (int i = 0; i < 16; i++) v[i] = row[i * 32 + lane];   // all loads in flight
    unsigned lt = (1u << lane) - 1u;
    int count = 0;
#pragma unroll
    for (int i = 0; i < 16; i++) {
        unsigned b0 = __ballot_sync(0xffffffffu, v[i].x != 0);
        unsigned b1 = __ballot_sync(0xffffffffu, v[i].y != 0);
        unsigned b2 = __ballot_sync(0xffffffffu, v[i].z != 0);
        unsigned b3 = __ballot_sync(0xffffffffu, v[i].w != 0);
        int prel = __popc(b0 & lt) + __popc(b1 & lt) + __popc(b2 & lt) + __popc(b3 & lt);
        int basepos = i * 128 + lane * 4;
        int slot = count + prel;
        if (v[i].x) { if (slot < NSENT) g_idx[b * NSENT + slot] = basepos + 0; slot++; }
        if (v[i].y) { if (slot < NSENT) g_idx[b * NSENT + slot] = basepos + 1; slot++; }
        if (v[i].z) { if (slot < NSENT) g_idx[b * NSENT + slot] = basepos + 2; slot++; }
        if (v[i].w) { if (slot < NSENT) g_idx[b * NSENT + slot] = basepos + 3; slot++; }
        count += __popc(b0) + __popc(b1) + __popc(b2) + __popc(b3);
    }
}

// ---------------- kernel 2: q + v GEMVs, split-K x8 (warp per partial) --
// 16384 warps; each dots a 512-float segment with all 8 LDG.128 batched.
__global__ __launch_bounds__(256) void qv_kernel(
    const float* __restrict__ hidden,
    const float* __restrict__ Wq, const float* __restrict__ Wr)
{
    int gw = blockIdx.x * 8 + (threadIdx.x >> 5);   // 0..16383
    int lane = threadIdx.x & 31;
    int sp   = gw & (QSPL - 1);
    int task = gw >> 3;                 // 0..2047
    const float4* x4;
    const float4* w4;
    if (task < BATCH * DDIM) {          // q task
        int b = task >> 7, d = task & 127;
        int row = g_idx[b * NSENT + NSENT - 1];
        x4 = (const float4*)(hidden + ((size_t)b * SEQ + row) * HDIM + sp * QSEG);
        w4 = (const float4*)(Wq + (size_t)d * HDIM + sp * QSEG);
    } else {                            // v task
        int tt = task - BATCH * DDIM;
        int b = tt >> 7, i = tt & 127;
        int row = g_idx[b * NSENT + i];
        x4 = (const float4*)(hidden + ((size_t)b * SEQ + row) * HDIM + sp * QSEG);
        w4 = (const float4*)(Wr + sp * QSEG);
    }
    float4 xa[4], wa[4];
#pragma unroll
    for (int it = 0; it < 4; it++) {    // all 8 LDG.128 in flight
        xa[it] = x4[it * 32 + lane];
        wa[it] = w4[it * 32 + lane];
    }
    float s = 0.f;
#pragma unroll
    for (int it = 0; it < 4; it++)
        s += xa[it].x * wa[it].x + xa[it].y * wa[it].y
           + xa[it].z * wa[it].z + xa[it].w * wa[it].w;
#pragma unroll
    for (int o = 16; o > 0; o >>= 1) s += __shfl_xor_sync(0xffffffffu, s, o);
    if (lane == 0) {
        if (task < BATCH * DDIM) g_qpart[sp * (BATCH * DDIM) + task] = s;
        else g_vpart[sp * (BATCH * NSENT) + task - BATCH * DDIM] = s;
    }
}

// ---------------- kernel 3: K projection via WMMA bf16 (3-term split) ----
// grid (KS2, 2*BATCH): b = by>>1, mhalf = by&1. 256 threads = 8 warps,
// CTA tile M=64 x N=128, warp tile 32x32. 2 CTAs/SM (regs<=128, smem 104KB).
// A raw dbl-buffered (cp.async 2 ahead), A bf16 tiles dbl, W single-buffered.
__global__ void __launch_bounds__(MMA_THREADS, 2)
mma_kernel(const float* __restrict__ hidden)
{
    extern __shared__ char smem[];
    __shared__ int idx_sh[MROWS];

    int t  = threadIdx.x;
    int sp = blockIdx.x;
    int b  = blockIdx.y >> 1, mh = blockIdx.y & 1;
    int wid = t >> 5;
    int warp_m = wid & 1;      // 0..1 -> m base = warp_m*32
    int warp_n = wid >> 1;     // 0..3 -> n base = warp_n*32

    const int k0 = sp * KSL;
    if (t < MROWS) idx_sh[t] = g_idx[b * NSENT + mh * MROWS + t];
    __syncthreads();

    wmma::fragment<wmma::accumulator, 16, 16, 16, float> acc[2][2];
#pragma unroll
    for (int i = 0; i < 2; i++)
#pragma unroll
        for (int j = 0; j < 2; j++) wmma::fill_fragment(acc[i][j], 0.0f);

    auto issueA = [&](int s) {
        int kk = k0 + s * STG;
        float* rawA = (float*)(smem + (s & 1) * RAWA_SZ);
#pragma unroll
        for (int i = 0; i < 4; i++) {             // 1024 float4 chunks / 256 thr
            int lin = t + MMA_THREADS * i, row = lin >> 4, c4 = lin & 15;
            cp_async16(smem_u32(rawA + row * STG + c4 * 4),
                       hidden + ((size_t)b * SEQ + idx_sh[row]) * HDIM + kk + c4 * 4);
        }
        CP_COMMIT();
    };
    auto issueW = [&](int s) {
        int kk = k0 + s * STG;
        char* wt = smem + WT_OFF;                 // single buffer
#pragma unroll
        for (int i = 0; i < 8; i++) {             // 2048 16B chunks (hi then lo)
            int lin = t + MMA_THREADS * i;
            int mat = lin >> 10;                  // 0=hi, 1=lo
            int rem = lin & 1023;
            int row = rem >> 3, ch = rem & 7;
            const __nv_bfloat16* src = (mat ? g_Wlo : g_Whi) + (size_t)row * HDIM + kk + ch * 8;
            cp_async16(smem_u32(wt + mat * WTILE + row * (TSTRIDE * 2) + ch * 16), src);
        }
        CP_COMMIT();
    };
    // convert 1/4 of stage s's raw A (256 chunks) into bf16 hi/lo tiles
    auto convert1 = [&](int s, int i) {
        const float4* rawA4 = (const float4*)(smem + (s & 1) * RAWA_SZ);
        __nv_bfloat16* Ahi = (__nv_bfloat16*)(smem + AT_OFF + (s & 1) * ASTAGE);
        __nv_bfloat16* Alo = (__nv_bfloat16*)((char*)Ahi + ATILE);
        int lin = t + MMA_THREADS * i, row = lin >> 4, c4 = lin & 15;
        float4 x = rawA4[row * 16 + c4];
        __nv_bfloat162 h0 = __floats2bfloat162_rn(x.x, x.y);
        __nv_bfloat162 h1 = __floats2bfloat162_rn(x.z, x.w);
        __nv_bfloat162 l0 = __floats2bfloat162_rn(x.x - __bfloat162float(h0.x),
                                                  x.y - __bfloat162float(h0.y));
        __nv_bfloat162 l1 = __floats2bfloat162_rn(x.z - __bfloat162float(h1.x),
                                                  x.w - __bfloat162float(h1.y));
        uint2 hv; hv.x = *(uint32_t*)&h0; hv.y = *(uint32_t*)&h1;
        uint2 lv; lv.x = *(uint32_t*)&l0; lv.y = *(uint32_t*)&l1;
        *(uint2*)(Ahi + row * TSTRIDE + c4 * 4) = hv;
        *(uint2*)(Alo + row * TSTRIDE + c4 * 4) = lv;
    };

    // prologue: A0, W0, A1 in flight; wait A0+W0
    issueA(0); issueW(0); issueA(1);
    CP_WAIT(1);
    __syncthreads();
    convert1(0, 0); convert1(0, 1); convert1(0, 2); convert1(0, 3);
    __syncthreads();

    for (int s = 0; s < NSTG; s++) {
        // at entry: W(s) issued (prologue or end of stage s-1), A(s+1) issued.
        if (s + 2 < NSTG) { issueA(s + 2); CP_WAIT(1); }  // forces A(s+1)+W(s) done
        else              { CP_WAIT(0); }
        __syncthreads();   // make cp.async data visible CTA-wide

        const __nv_bfloat16* Ah = (const __nv_bfloat16*)(smem + AT_OFF + (s & 1) * ASTAGE);
        const __nv_bfloat16* Al = (const __nv_bfloat16*)((char*)Ah + ATILE);
        const __nv_bfloat16* Wh = (const __nv_bfloat16*)(smem + WT_OFF);
        const __nv_bfloat16* Wl = (const __nv_bfloat16*)(smem + WT_OFF + WTILE);
        const __nv_bfloat16* Ab  = Ah + warp_m * 32 * TSTRIDE;
        const __nv_bfloat16* Lb  = Al + warp_m * 32 * TSTRIDE;
        const __nv_bfloat16* WhB = Wh + warp_n * 32 * TSTRIDE;
        const __nv_bfloat16* WlB = Wl + warp_n * 32 * TSTRIDE;

#pragma unroll
        for (int kk = 0; kk < STG / 16; kk++) {
            wmma::fragment<wmma::matrix_a, 16, 16, 16, __nv_bfloat16, wmma::row_major> ah[2], al[2];
            wmma::fragment<wmma::matrix_b, 16, 16, 16, __nv_bfloat16, wmma::col_major> wh[2], wl[2];
#pragma unroll
            for (int i = 0; i < 2; i++) {
                wmma::load_matrix_sync(ah[i], Ab + i * 16 * TSTRIDE + kk * 16, TSTRIDE);
                wmma::load_matrix_sync(al[i], Lb + i * 16 * TSTRIDE + kk * 16, TSTRIDE);
            }
#pragma unroll
            for (int j = 0; j < 2; j++) {
                wmma::load_matrix_sync(wh[j], WhB + j * 16 * TSTRIDE + kk * 16, TSTRIDE);
                wmma::load_matrix_sync(wl[j], WlB + j * 16 * TSTRIDE + kk * 16, TSTRIDE);
            }
#pragma unroll
            for (int i = 0; i < 2; i++)
#pragma unroll
                for (int j = 0; j < 2; j++) {
                    wmma::mma_sync(acc[i][j], ah[i], wh[j], acc[i][j]);
                    wmma::mma_sync(acc[i][j], ah[i], wl[j], acc[i][j]);
                    wmma::mma_sync(acc[i][j], al[i], wh[j], acc[i][j]);
                }
            if (s + 1 < NSTG) convert1(s + 1, kk);   // overlap convert with HMMAs
        }
        __syncthreads();                  // everyone done reading W + tiles written
        if (s + 1 < NSTG) issueW(s + 1);  // refill single W buffer
    }

    // ---- epilogue: store split-K partial (this CTA's 64-row half) ----
    float* out = g_part + (((size_t)(sp * BATCH + b)) << 14) + (size_t)mh * MROWS * DDIM;
#pragma unroll
    for (int i = 0; i < 2; i++)
#pragma unroll
        for (int j = 0; j < 2; j++)
            wmma::store_matrix_sync(out + (size_t)(warp_m * 32 + i * 16) * DDIM
                                        + warp_n * 32 + j * 16,
                                    acc[i][j], DDIM, wmma::mem_row_major);
}

// ---------------- kernel 4: split-K reduce + bias + RoPE (float2) ----
__global__ __launch_bounds__(256) void kred_kernel(const float* __restrict__ bk) {
    int p = blockIdx.x * 256 + threadIdx.x;       // pair id over B*NS*64 = 65536
    if (p >= BATCH * NSENT * 64) return;
    int b = p >> 13;
    int t = (p >> 6) & 127;                        // sentence index
    int j = p & 63;                                // rotation pair
    int off2 = p & 8191;                           // (t*64 + j)
    float2 s = ((const float2*)bk)[j];
#pragma unroll
    for (int sp = 0; sp < KS2; sp++) {
        float2 v = ((const float2*)g_part)[(((size_t)(sp * BATCH + b)) << 13) + off2];
        s.x += v.x; s.y += v.y;
    }
    // RoPE at position t:  f = theta^(-j/64) = exp2(-j * log2(1e4)/64)
    float f = exp2f(-(float)j * 0.20762050593045163f);
    float ang = (float)t * f;
    float sn, cs; sincosf(ang, &sn, &cs);
    float2 o;
    o.x = s.x * cs - s.y * sn;
    o.y = s.x * sn + s.y * cs;
    ((float2*)g_kf)[p] = o;
}

// ---------------- kernel 5: attention + rewards ----------------------
__global__ __launch_bounds__(128) void finalize_kernel(float* __restrict__ out,
                                                       const float* __restrict__ bq,
                                                       const float* __restrict__ br) {
    __shared__ float qfull[DDIM];
    __shared__ float qsh[DDIM];
    __shared__ float red[NSENT];
    __shared__ float vsh[NSENT];
    int b = blockIdx.x, t = threadIdx.x;

    const double LN1E4   = 9.210340371976184;      // ln(10000)
    const double INV_2PI = 0.15915494309189535;
    const double TWO_PI  = 6.283185307179586;

    // reduce v partials (deterministic order) + bias
    {
        float v = br[0];
#pragma unroll
        for (int sp = 0; sp < QSPL; sp++)
            v += g_vpart[sp * (BATCH * NSENT) + b * NSENT + t];
        vsh[t] = v;
    }
    // reduce q partials (deterministic order) + bias
    {
        float qv = bq[t];
#pragma unroll
        for (int sp = 0; sp < QSPL; sp++)
            qv += g_qpart[sp * (BATCH * DDIM) + b * DDIM + t];
        qfull[t] = qv;
    }
    __syncthreads();

    // RoPE q at position NSENT-1, pre-scaled by 1/sqrt(D)
    if (t < DDIM / 2) {
        double f   = exp(-((double)(2 * t) / (double)DDIM) * LN1E4);
        double ang = (double)(NSENT - 1) * f;
        double kk  = rint(ang * INV_2PI);
        float  ar  = (float)(ang - kk * TWO_PI);
        float c, sn; sincosf(ar, &sn, &c);
        float re = qfull[2 * t], im = qfull[2 * t + 1];
        const float isd = 0.08838834764831845f;    // 1/sqrt(128)
        qsh[2 * t]     = (re * c - im * sn) * isd;
        qsh[2 * t + 1] = (re * sn + im * c) * isd;
    }
    __syncthreads();

    // logit_t = rope(k_t) . rope(q)/sqrt(D)  (k already rotated in kred)
    const float4* krow = (const float4*)(g_kf + ((size_t)b << 14) + (size_t)t * DDIM);
    const float4* q4   = (const float4*)qsh;
    float logit = 0.f;
#pragma unroll
    for (int j = 0; j < DDIM / 4; j++) {
        float4 k4 = krow[j], qq = q4[j];
        logit += k4.x * qq.x + k4.y * qq.y + k4.z * qq.z + k4.w * qq.w;
    }

    // softmax over the 128 sentences
    red[t] = logit; __syncthreads();
#pragma unroll
    for (int o = 64; o > 0; o >>= 1) { if (t < o) red[t] = fmaxf(red[t], red[t + o]); __syncthreads(); }
    float mx = red[0]; __syncthreads();
    float e = expf(logit - mx);
    red[t] = e; __syncthreads();
#pragma unroll
    for (int o = 64; o > 0; o >>= 1) { if (t < o) red[t] += red[t + o]; __syncthreads(); }
    float ssum = red[0]; __syncthreads();
    float attn = e / ssum;

    float v  = vsh[t];
    float sr = (t == 0) ? v : (v - vsh[t - 1]);
    float srw = sr * attn;
    out[b * NSENT + t] = srw;

    red[t] = srw; __syncthreads();
#pragma unroll
    for (int o = 64; o > 0; o >>= 1) { if (t < o) red[t] += red[t + o]; __syncthreads(); }
    if (t == 0) out[BATCH * NSENT + b] = red[0];
}

// ---------------- host launcher ----------------
extern "C" void kernel_launch(void* const* d_in, const int* in_sizes, int n_in,
                              void* d_out, int out_size) {
    const float* hidden = (const float*)d_in[0];
    const int*   mask   = (const int*)d_in[1];
    int off = (n_in > 2 && in_sizes[2] == 1) ? 3 : 2;
    const float* Wq = (const float*)d_in[off + 0];
    const float* bq = (const float*)d_in[off + 1];
    const float* Wk = (const float*)d_in[off + 2];
    const float* bk = (const float*)d_in[off + 3];
    const float* Wr = (const float*)d_in[off + 4];
    const float* br = (const float*)d_in[off + 5];
    float* out = (float*)d_out;

    cudaFuncSetAttribute(mma_kernel, cudaFuncAttributeMaxDynamicSharedMemorySize,
                         MMA_SMEM_TOTAL);

    prepw_kernel<<<DDIM * HDIM / 4 / 256, 256>>>(Wk);
    idx_kernel<<<BATCH, 32>>>(mask);
    qv_kernel<<<QSPL * 2 * BATCH * NSENT / 8, 256>>>(hidden, Wq, Wr);
    mma_kernel<<<dim3(KS2, 2 * BATCH), MMA_THREADS, MMA_SMEM_TOTAL>>>(hidden);
    kred_kernel<<<(BATCH * NSENT * 64 + 255) / 256, 256>>>(bk);
    finalize_kernel<<<BATCH, 128>>>(out, bq, br);
    (void)in_sizes; (void)n_in; (void)out_size;
}

// round 14
// speedup vs baseline: 1.0214x; 1.0214x over previous
#include <cuda_runtime.h>
#include <cuda_bf16.h>
#include <mma.h>
#include <math.h>
#include <cstdint>

using namespace nvcuda;

// Problem constants (fixed by the dataset)
#define BATCH 8
#define SEQ   2048
#define HDIM  4096
#define DDIM  128
#define NSENT 128

// split-K for the HMMA GEMM
#define KS2   16
#define KSL   (HDIM / KS2)     // 256 fp32 k per CTA
#define STG   64               // k per pipeline stage
#define NSTG  (KSL / STG)      // 4 stages
#define MMA_THREADS 256        // 8 warps; CTA tile M=64 x N=128
#define MROWS 64               // sentence rows per CTA (M-split x2)

// split-K for the q/v GEMVs
#define QSPL  8
#define QSEG  (HDIM / QSPL)    // 512 floats per warp segment

#define TSTRIDE 72                     // bf16 tile row stride (144B)
#define ATILE   (MROWS * TSTRIDE * 2)  // 9216 bytes per A bf16 tile (64 rows)
#define ASTAGE  (2 * ATILE)            // hi+lo = 18432
#define WTILE   (128 * TSTRIDE * 2)    // 18432 bytes per W bf16 tile (128 rows)
#define WT_OFF  (2 * ASTAGE)           // 36864: W double-buffered (hi,lo)x2
#define MMA_SMEM_TOTAL (WT_OFF + 2 * 2 * WTILE)   // 110592 bytes -> 2 CTAs/SM

// ---------------- scratch (no allocations allowed) ----------------
__device__ int   g_idx[BATCH * NSENT];
__device__ float g_qpart[QSPL * BATCH * DDIM];               // 32 KB
__device__ float g_vpart[QSPL * BATCH * NSENT];              // 32 KB
__device__ float g_part[(size_t)KS2 * BATCH * NSENT * DDIM]; // 8 MB fp32 partials
__device__ float g_kf [(size_t)BATCH * NSENT * DDIM];        // 512 KB (RoPE'd K)
__device__ __nv_bfloat16 g_Whi[(size_t)DDIM * HDIM];         // 1 MB
__device__ __nv_bfloat16 g_Wlo[(size_t)DDIM * HDIM];         // 1 MB

// ---------------- PTX helpers (baseline compute_103 only!) ----------------
__device__ __forceinline__ uint32_t smem_u32(const void* p) {
    uint32_t a;
    asm("{ .reg .u64 t; cvta.to.shared.u64 t, %1; cvt.u32.u64 %0, t; }" : "=r"(a) : "l"(p));
    return a;
}
__device__ __forceinline__ void cp_async16(uint32_t saddr, const void* g) {
    asm volatile("cp.async.cg.shared.global [%0], [%1], 16;" :: "r"(saddr), "l"(g));
}
#define CP_COMMIT() asm volatile("cp.async.commit_group;" ::: "memory")
#define CP_WAIT(n)  asm volatile("cp.async.wait_group %0;" :: "n"(n) : "memory")

// ---------------- kernel 0: pre-split Wk into hi/lo bf16 ----------------
__global__ __launch_bounds__(256) void prepw_kernel(const float* __restrict__ Wk) {
    int i = blockIdx.x * 256 + threadIdx.x;       // over DDIM*HDIM/4 = 131072 float4
    if (i >= DDIM * HDIM / 4) return;
    float4 x = ((const float4*)Wk)[i];
    __nv_bfloat162 h0 = __floats2bfloat162_rn(x.x, x.y);
    __nv_bfloat162 h1 = __floats2bfloat162_rn(x.z, x.w);
    __nv_bfloat162 l0 = __floats2bfloat162_rn(x.x - __bfloat162float(h0.x),
                                              x.y - __bfloat162float(h0.y));
    __nv_bfloat162 l1 = __floats2bfloat162_rn(x.z - __bfloat162float(h1.x),
                                              x.w - __bfloat162float(h1.y));
    uint2 hv; hv.x = *(uint32_t*)&h0; hv.y = *(uint32_t*)&h1;
    uint2 lv; lv.x = *(uint32_t*)&l0; lv.y = *(uint32_t*)&l1;
    ((uint2*)g_Whi)[i] = hv;
    ((uint2*)g_Wlo)[i] = lv;
}

// ---------------- kernel 1: extract sentence positions (MLP-64) --------
__global__ void idx_kernel(const int* __restrict__ mask) {
    int b = blockIdx.x;
    int lane = threadIdx.x;            // 32 threads
    const int4* row = (const int4*)(mask + (size_t)b * SEQ);
    int4 v[16];
#pragma unroll
    for (int i = 0; i < 16; i++) v[i] = row[i * 32 + lane];   // all loads in flight
    unsigned lt = (1u << lane) - 1u;
    int count = 0;
#pragma unroll
    for (int i = 0; i < 16; i++) {
        unsigned b0 = __ballot_sync(0xffffffffu, v[i].x != 0);
        unsigned b1 = __ballot_sync(0xffffffffu, v[i].y != 0);
        unsigned b2 = __ballot_sync(0xffffffffu, v[i].z != 0);
        unsigned b3 = __ballot_sync(0xffffffffu, v[i].w != 0);
        int prel = __popc(b0 & lt) + __popc(b1 & lt) + __popc(b2 & lt) + __popc(b3 & lt);
        int basepos = i * 128 + lane * 4;
        int slot = count + prel;
        if (v[i].x) { if (slot < NSENT) g_idx[b * NSENT + slot] = basepos + 0; slot++; }
        if (v[i].y) { if (slot < NSENT) g_idx[b * NSENT + slot] = basepos + 1; slot++; }
        if (v[i].z) { if (slot < NSENT) g_idx[b * NSENT + slot] = basepos + 2; slot++; }
        if (v[i].w) { if (slot < NSENT) g_idx[b * NSENT + slot] = basepos + 3; slot++; }
        count += __popc(b0) + __popc(b1) + __popc(b2) + __popc(b3);
    }
}

// ---------------- kernel 2: q + v GEMVs, split-K x8 (warp per partial) --
// 16384 warps; each dots a 512-float segment with all 8 LDG.128 batched.
__global__ __launch_bounds__(256) void qv_kernel(
    const float* __restrict__ hidden,
    const float* __restrict__ Wq, const float* __restrict__ Wr)
{
    int gw = blockIdx.x * 8 + (threadIdx.x >> 5);   // 0..16383
    int lane = threadIdx.x & 31;
    int sp   = gw & (QSPL - 1);
    int task = gw >> 3;                 // 0..2047
    const float4* x4;
    const float4* w4;
    if (task < BATCH * DDIM) {          // q task
        int b = task >> 7, d = task & 127;
        int row = g_idx[b * NSENT + NSENT - 1];
        x4 = (const float4*)(hidden + ((size_t)b * SEQ + row) * HDIM + sp * QSEG);
        w4 = (const float4*)(Wq + (size_t)d * HDIM + sp * QSEG);
    } else {                            // v task
        int tt = task - BATCH * DDIM;
        int b = tt >> 7, i = tt & 127;
        int row = g_idx[b * NSENT + i];
        x4 = (const float4*)(hidden + ((size_t)b * SEQ + row) * HDIM + sp * QSEG);
        w4 = (const float4*)(Wr + sp * QSEG);
    }
    float4 xa[4], wa[4];
#pragma unroll
    for (int it = 0; it < 4; it++) {    // all 8 LDG.128 in flight
        xa[it] = x4[it * 32 + lane];
        wa[it] = w4[it * 32 + lane];
    }
    float s = 0.f;
#pragma unroll
    for (int it = 0; it < 4; it++)
        s += xa[it].x * wa[it].x + xa[it].y * wa[it].y
           + xa[it].z * wa[it].z + xa[it].w * wa[it].w;
#pragma unroll
    for (int o = 16; o > 0; o >>= 1) s += __shfl_xor_sync(0xffffffffu, s, o);
    if (lane == 0) {
        if (task < BATCH * DDIM) g_qpart[sp * (BATCH * DDIM) + task] = s;
        else g_vpart[sp * (BATCH * NSENT) + task - BATCH * DDIM] = s;
    }
}

// ---------------- kernel 3: K projection via WMMA bf16 (3-term split) ----
// grid (KS2, 2*BATCH), 256 threads = 8 warps, CTA tile M=64 x N=128.
// A gathered fp32 -> REGISTERS (prefetched 1 stage ahead), converted to
// bf16 hi/lo tiles at stage start. W bf16 double-buffered via cp.async,
// issued 2 stages ahead. 2 CTAs/SM. Zero exposed load latency steady-state.
__global__ void __launch_bounds__(MMA_THREADS, 2)
mma_kernel(const float* __restrict__ hidden)
{
    extern __shared__ char smem[];
    __shared__ int idx_sh[MROWS];

    int t  = threadIdx.x;
    int sp = blockIdx.x;
    int b  = blockIdx.y >> 1, mh = blockIdx.y & 1;
    int wid = t >> 5;
    int warp_m = wid & 1;      // 0..1 -> m base = warp_m*32
    int warp_n = wid >> 1;     // 0..3 -> n base = warp_n*32

    const int k0 = sp * KSL;
    if (t < MROWS) idx_sh[t] = g_idx[b * NSENT + mh * MROWS + t];
    __syncthreads();

    // per-thread A chunk addressing: 1024 float4 chunks / 256 threads = 4
    const float* aptr[4];
    int soff[4];
#pragma unroll
    for (int i = 0; i < 4; i++) {
        int lin = t + MMA_THREADS * i;
        int row = lin >> 4, c4 = lin & 15;
        aptr[i] = hidden + ((size_t)b * SEQ + idx_sh[row]) * HDIM + c4 * 4;
        soff[i] = row * TSTRIDE + c4 * 4;     // bf16 element offset in tile
    }
    float4 areg[4];

    wmma::fragment<wmma::accumulator, 16, 16, 16, float> acc[2][2];
#pragma unroll
    for (int i = 0; i < 2; i++)
#pragma unroll
        for (int j = 0; j < 2; j++) wmma::fill_fragment(acc[i][j], 0.0f);

    auto loadA = [&](int s) {             // plain LDG.128 into regs
        int kk = k0 + s * STG;
#pragma unroll
        for (int i = 0; i < 4; i++) areg[i] = *(const float4*)(aptr[i] + kk);
    };
    auto convertA = [&](int s) {          // regs -> bf16 hi/lo tiles
        __nv_bfloat16* Ahi = (__nv_bfloat16*)(smem + (s & 1) * ASTAGE);
        __nv_bfloat16* Alo = (__nv_bfloat16*)((char*)Ahi + ATILE);
#pragma unroll
        for (int i = 0; i < 4; i++) {
            float4 x = areg[i];
            __nv_bfloat162 h0 = __floats2bfloat162_rn(x.x, x.y);
            __nv_bfloat162 h1 = __floats2bfloat162_rn(x.z, x.w);
            __nv_bfloat162 l0 = __floats2bfloat162_rn(x.x - __bfloat162float(h0.x),
                                                      x.y - __bfloat162float(h0.y));
            __nv_bfloat162 l1 = __floats2bfloat162_rn(x.z - __bfloat162float(h1.x),
                                                      x.w - __bfloat162float(h1.y));
            uint2 hv; hv.x = *(uint32_t*)&h0; hv.y = *(uint32_t*)&h1;
            uint2 lv; lv.x = *(uint32_t*)&l0; lv.y = *(uint32_t*)&l1;
            *(uint2*)(Ahi + soff[i]) = hv;
            *(uint2*)(Alo + soff[i]) = lv;
        }
    };
    auto issueW = [&](int s) {
        int kk = k0 + s * STG;
        char* wt = smem + WT_OFF + (s & 1) * (2 * WTILE);
#pragma unroll
        for (int i = 0; i < 8; i++) {     // 2048 16B chunks (hi then lo)
            int lin = t + MMA_THREADS * i;
            int mat = lin >> 10;          // 0=hi, 1=lo
            int rem = lin & 1023;
            int row = rem >> 3, ch = rem & 7;
            const __nv_bfloat16* src = (mat ? g_Wlo : g_Whi) + (size_t)row * HDIM + kk + ch * 8;
            cp_async16(smem_u32(wt + mat * WTILE + row * (TSTRIDE * 2) + ch * 16), src);
        }
        CP_COMMIT();
    };

    // prologue: W0 + W1 in flight; A0 in regs
    issueW(0); issueW(1); loadA(0);

    for (int s = 0; s < NSTG; s++) {
        convertA(s);                              // write tiles buf (s&1)
        if (s == NSTG - 1) { CP_WAIT(0); } else { CP_WAIT(1); }  // W(s) done
        __syncthreads();                          // tiles + W visible CTA-wide
        if (s + 1 < NSTG) loadA(s + 1);           // prefetch next A (hidden)

        const __nv_bfloat16* Ah = (const __nv_bfloat16*)(smem + (s & 1) * ASTAGE);
        const __nv_bfloat16* Al = (const __nv_bfloat16*)((char*)Ah + ATILE);
        const __nv_bfloat16* Wh = (const __nv_bfloat16*)(smem + WT_OFF + (s & 1) * (2 * WTILE));
        const __nv_bfloat16* Wl = (const __nv_bfloat16*)((char*)Wh + WTILE);
        const __nv_bfloat16* Ab  = Ah + warp_m * 32 * TSTRIDE;
        const __nv_bfloat16* Lb  = Al + warp_m * 32 * TSTRIDE;
        const __nv_bfloat16* WhB = Wh + warp_n * 32 * TSTRIDE;
        const __nv_bfloat16* WlB = Wl + warp_n * 32 * TSTRIDE;

#pragma unroll
        for (int kk = 0; kk < STG / 16; kk++) {
            wmma::fragment<wmma::matrix_a, 16, 16, 16, __nv_bfloat16, wmma::row_major> ah[2], al[2];
            wmma::fragment<wmma::matrix_b, 16, 16, 16, __nv_bfloat16, wmma::col_major> wh[2], wl[2];
#pragma unroll
            for (int i = 0; i < 2; i++) {
                wmma::load_matrix_sync(ah[i], Ab + i * 16 * TSTRIDE + kk * 16, TSTRIDE);
                wmma::load_matrix_sync(al[i], Lb + i * 16 * TSTRIDE + kk * 16, TSTRIDE);
            }
#pragma unroll
            for (int j = 0; j < 2; j++) {
                wmma::load_matrix_sync(wh[j], WhB + j * 16 * TSTRIDE + kk * 16, TSTRIDE);
                wmma::load_matrix_sync(wl[j], WlB + j * 16 * TSTRIDE + kk * 16, TSTRIDE);
            }
#pragma unroll
            for (int i = 0; i < 2; i++)
#pragma unroll
                for (int j = 0; j < 2; j++) {
                    wmma::mma_sync(acc[i][j], ah[i], wh[j], acc[i][j]);
                    wmma::mma_sync(acc[i][j], ah[i], wl[j], acc[i][j]);
                    wmma::mma_sync(acc[i][j], al[i], wh[j], acc[i][j]);
                }
        }
        __syncthreads();                  // all warps done reading W buf (s&1)
        if (s + 2 < NSTG) issueW(s + 2);  // refill the buffer just freed
    }

    // ---- epilogue: store split-K partial (this CTA's 64-row half) ----
    float* out = g_part + (((size_t)(sp * BATCH + b)) << 14) + (size_t)mh * MROWS * DDIM;
#pragma unroll
    for (int i = 0; i < 2; i++)
#pragma unroll
        for (int j = 0; j < 2; j++)
            wmma::store_matrix_sync(out + (size_t)(warp_m * 32 + i * 16) * DDIM
                                        + warp_n * 32 + j * 16,
                                    acc[i][j], DDIM, wmma::mem_row_major);
}

// ---------------- kernel 4: split-K reduce + bias + RoPE (float2) ----
__global__ __launch_bounds__(256) void kred_kernel(const float* __restrict__ bk) {
    int p = blockIdx.x * 256 + threadIdx.x;       // pair id over B*NS*64 = 65536
    if (p >= BATCH * NSENT * 64) return;
    int b = p >> 13;
    int t = (p >> 6) & 127;                        // sentence index
    int j = p & 63;                                // rotation pair
    int off2 = p & 8191;                           // (t*64 + j)
    float2 s = ((const float2*)bk)[j];
#pragma unroll
    for (int sp = 0; sp < KS2; sp++) {
        float2 v = ((const float2*)g_part)[(((size_t)(sp * BATCH + b)) << 13) + off2];
        s.x += v.x; s.y += v.y;
    }
    // RoPE at position t:  f = theta^(-j/64) = exp2(-j * log2(1e4)/64)
    float f = exp2f(-(float)j * 0.20762050593045163f);
    float ang = (float)t * f;
    float sn, cs; sincosf(ang, &sn, &cs);
    float2 o;
    o.x = s.x * cs - s.y * sn;
    o.y = s.x * sn + s.y * cs;
    ((float2*)g_kf)[p] = o;
}

// ---------------- kernel 5: attention + rewards ----------------------
__global__ __launch_bounds__(128) void finalize_kernel(float* __restrict__ out,
                                                       const float* __restrict__ bq,
                                                       const float* __restrict__ br) {
    __shared__ float qfull[DDIM];
    __shared__ float qsh[DDIM];
    __shared__ float red[NSENT];
    __shared__ float vsh[NSENT];
    int b = blockIdx.x, t = threadIdx.x;

    const double LN1E4   = 9.210340371976184;      // ln(10000)
    const double INV_2PI = 0.15915494309189535;
    const double TWO_PI  = 6.283185307179586;

    // reduce v partials (deterministic order) + bias
    {
        float v = br[0];
#pragma unroll
        for (int sp = 0; sp < QSPL; sp++)
            v += g_vpart[sp * (BATCH * NSENT) + b * NSENT + t];
        vsh[t] = v;
    }
    // reduce q partials (deterministic order) + bias
    {
        float qv = bq[t];
#pragma unroll
        for (int sp = 0; sp < QSPL; sp++)
            qv += g_qpart[sp * (BATCH * DDIM) + b * DDIM + t];
        qfull[t] = qv;
    }
    __syncthreads();

    // RoPE q at position NSENT-1, pre-scaled by 1/sqrt(D)
    if (t < DDIM / 2) {
        double f   = exp(-((double)(2 * t) / (double)DDIM) * LN1E4);
        double ang = (double)(NSENT - 1) * f;
        double kk  = rint(ang * INV_2PI);
        float  ar  = (float)(ang - kk * TWO_PI);
        float c, sn; sincosf(ar, &sn, &c);
        float re = qfull[2 * t], im = qfull[2 * t + 1];
        const float isd = 0.08838834764831845f;    // 1/sqrt(128)
        qsh[2 * t]     = (re * c - im * sn) * isd;
        qsh[2 * t + 1] = (re * sn + im * c) * isd;
    }
    __syncthreads();

    // logit_t = rope(k_t) . rope(q)/sqrt(D)  (k already rotated in kred)
    const float4* krow = (const float4*)(g_kf + ((size_t)b << 14) + (size_t)t * DDIM);
    const float4* q4   = (const float4*)qsh;
    float logit = 0.f;
#pragma unroll
    for (int j = 0; j < DDIM / 4; j++) {
        float4 k4 = krow[j], qq = q4[j];
        logit += k4.x * qq.x + k4.y * qq.y + k4.z * qq.z + k4.w * qq.w;
    }

    // softmax over the 128 sentences
    red[t] = logit; __syncthreads();
#pragma unroll
    for (int o = 64; o > 0; o >>= 1) { if (t < o) red[t] = fmaxf(red[t], red[t + o]); __syncthreads(); }
    float mx = red[0]; __syncthreads();
    float e = expf(logit - mx);
    red[t] = e; __syncthreads();
#pragma unroll
    for (int o = 64; o > 0; o >>= 1) { if (t < o) red[t] += red[t + o]; __syncthreads(); }
    float ssum = red[0]; __syncthreads();
    float attn = e / ssum;

    float v  = vsh[t];
    float sr = (t == 0) ? v : (v - vsh[t - 1]);
    float srw = sr * attn;
    out[b * NSENT + t] = srw;

    red[t] = srw; __syncthreads();
#pragma unroll
    for (int o = 64; o > 0; o >>= 1) { if (t < o) red[t] += red[t + o]; __syncthreads(); }
    if (t == 0) out[BATCH * NSENT + b] = red[0];
}

// ---------------- host launcher (fork qv onto a side stream) ----------
extern "C" void kernel_launch(void* const* d_in, const int* in_sizes, int n_in,
                              void* d_out, int out_size) {
    const float* hidden = (const float*)d_in[0];
    const int*   mask   = (const int*)d_in[1];
    int off = (n_in > 2 && in_sizes[2] == 1) ? 3 : 2;
    const float* Wq = (const float*)d_in[off + 0];
    const float* bq = (const float*)d_in[off + 1];
    const float* Wk = (const float*)d_in[off + 2];
    const float* bk = (const float*)d_in[off + 3];
    const float* Wr = (const float*)d_in[off + 4];
    const float* br = (const float*)d_in[off + 5];
    float* out = (float*)d_out;

    cudaFuncSetAttribute(mma_kernel, cudaFuncAttributeMaxDynamicSharedMemorySize,
                         MMA_SMEM_TOTAL);

    // try to fork qv onto a side stream (created per-call; only the
    // correctness/capture calls execute this host code — replays are graph-only)
    cudaStream_t side = 0;
    cudaEvent_t e1 = 0, e2 = 0;
    bool forked = (cudaStreamCreateWithFlags(&side, cudaStreamNonBlocking) == cudaSuccess);
    if (forked) forked = (cudaEventCreateWithFlags(&e1, cudaEventDisableTiming) == cudaSuccess);
    if (forked) forked = (cudaEventCreateWithFlags(&e2, cudaEventDisableTiming) == cudaSuccess);

    idx_kernel<<<BATCH, 32>>>(mask);
    if (forked) {
        cudaEventRecord(e1, 0);
        cudaStreamWaitEvent(side, e1, 0);
        qv_kernel<<<QSPL * 2 * BATCH * NSENT / 8, 256, 0, side>>>(hidden, Wq, Wr);
        cudaEventRecord(e2, side);
    } else {
        qv_kernel<<<QSPL * 2 * BATCH * NSENT / 8, 256>>>(hidden, Wq, Wr);
    }
    prepw_kernel<<<DDIM * HDIM / 4 / 256, 256>>>(Wk);
    mma_kernel<<<dim3(KS2, 2 * BATCH), MMA_THREADS, MMA_SMEM_TOTAL>>>(hidden);
    kred_kernel<<<(BATCH * NSENT * 64 + 255) / 256, 256>>>(bk);
    if (forked) cudaStreamWaitEvent(0, e2, 0);
    finalize_kernel<<<BATCH, 128>>>(out, bq, br);
    // note: stream/events intentionally leaked — destroying them mid-capture
    // would invalidate the captured graph; only ~2 host calls ever run this.
    (void)in_sizes; (void)n_in; (void)out_size;
}

// round 15
// speedup vs baseline: 1.2602x; 1.2337x over previous
#include <cuda_runtime.h>
#include <cuda_bf16.h>
#include <cuda_fp16.h>
#include <mma.h>
#include <math.h>
#include <cstdint>

using namespace nvcuda;

// Problem constants (fixed by the dataset)
#define BATCH 8
#define SEQ   2048
#define HDIM  4096
#define DDIM  128
#define NSENT 128

// split-K for the HMMA GEMM
#define KS2   16
#define KSL   (HDIM / KS2)     // 256 fp32 k per CTA
#define STG   64               // k per stage
#define NSTG  (KSL / STG)      // 4 A-stages; 8 mma-stages (Wl pass + Wh pass)
#define MMA_THREADS 256        // 8 warps; CTA tile M=64 x N=128
#define MROWS 64               // sentence rows per CTA (M-split x2)

// split-K for the q/v GEMVs
#define QSPL  8
#define QSEG  (HDIM / QSPL)    // 512 floats per warp segment

#define TSTRIDE 72                       // fp16 tile row stride (144B)
#define ATILE_H (MROWS * TSTRIDE * 2)    // 9216 B per A fp16 stage tile
#define A_TOTAL (NSTG * ATILE_H)         // 36864 B (all 4 stages resident)
#define WTILE_H (128 * TSTRIDE * 2)      // 18432 B per W fp16 stage tile
#define WBUFS   3
#define MMA_SMEM_TOTAL (A_TOTAL + WBUFS * WTILE_H)   // 92160 B -> 2 CTAs/SM

// ---------------- scratch (no allocations allowed) ----------------
__device__ int   g_idx[BATCH * NSENT];
__device__ float g_qpart[QSPL * BATCH * DDIM];               // 32 KB
__device__ float g_vpart[QSPL * BATCH * NSENT];              // 32 KB
__device__ float g_part[(size_t)KS2 * BATCH * NSENT * DDIM]; // 8 MB fp32 partials
__device__ float g_kf [(size_t)BATCH * NSENT * DDIM];        // 512 KB (RoPE'd K)
__device__ __half g_Whf[(size_t)DDIM * HDIM];                // 1 MB  fp16(W)
__device__ __half g_Wlf[(size_t)DDIM * HDIM];                // 1 MB  fp16((W-Whf)*4096)

// ---------------- PTX helpers (baseline compute_103 only!) ----------------
__device__ __forceinline__ uint32_t smem_u32(const void* p) {
    uint32_t a;
    asm("{ .reg .u64 t; cvta.to.shared.u64 t, %1; cvt.u32.u64 %0, t; }" : "=r"(a) : "l"(p));
    return a;
}
__device__ __forceinline__ void cp_async16(uint32_t saddr, const void* g) {
    asm volatile("cp.async.cg.shared.global [%0], [%1], 16;" :: "r"(saddr), "l"(g));
}
#define CP_COMMIT() asm volatile("cp.async.commit_group;" ::: "memory")
#define CP_WAIT(n)  asm volatile("cp.async.wait_group %0;" :: "n"(n) : "memory")

// ---------------- kernel A: fused idx (blocks 0-7) + W pre-split (rest) ----
__global__ __launch_bounds__(256) void prep_kernel(const int* __restrict__ mask,
                                                   const float* __restrict__ Wk) {
    if (blockIdx.x < BATCH) {
        // sentence-position extraction, MLP-64, warp 0 only
        if (threadIdx.x >= 32) return;
        int b = blockIdx.x;
        int lane = threadIdx.x;
        const int4* row = (const int4*)(mask + (size_t)b * SEQ);
        int4 v[16];
#pragma unroll
        for (int i = 0; i < 16; i++) v[i] = row[i * 32 + lane];
        unsigned lt = (1u << lane) - 1u;
        int count = 0;
#pragma unroll
        for (int i = 0; i < 16; i++) {
            unsigned b0 = __ballot_sync(0xffffffffu, v[i].x != 0);
            unsigned b1 = __ballot_sync(0xffffffffu, v[i].y != 0);
            unsigned b2 = __ballot_sync(0xffffffffu, v[i].z != 0);
            unsigned b3 = __ballot_sync(0xffffffffu, v[i].w != 0);
            int prel = __popc(b0 & lt) + __popc(b1 & lt) + __popc(b2 & lt) + __popc(b3 & lt);
            int basepos = i * 128 + lane * 4;
            int slot = count + prel;
            if (v[i].x) { if (slot < NSENT) g_idx[b * NSENT + slot] = basepos + 0; slot++; }
            if (v[i].y) { if (slot < NSENT) g_idx[b * NSENT + slot] = basepos + 1; slot++; }
            if (v[i].z) { if (slot < NSENT) g_idx[b * NSENT + slot] = basepos + 2; slot++; }
            if (v[i].w) { if (slot < NSENT) g_idx[b * NSENT + slot] = basepos + 3; slot++; }
            count += __popc(b0) + __popc(b1) + __popc(b2) + __popc(b3);
        }
        return;
    }
    // W pre-split: Whf = fp16(W); Wlf = fp16((W - Whf) * 4096)  (4096 exact)
    int i = (blockIdx.x - BATCH) * 256 + threadIdx.x;   // over DDIM*HDIM/4
    if (i >= DDIM * HDIM / 4) return;
    float4 x = ((const float4*)Wk)[i];
    __half2 h0 = __floats2half2_rn(x.x, x.y);
    __half2 h1 = __floats2half2_rn(x.z, x.w);
    __half2 l0 = __floats2half2_rn((x.x - __low2float(h0)) * 4096.0f,
                                   (x.y - __high2float(h0)) * 4096.0f);
    __half2 l1 = __floats2half2_rn((x.z - __low2float(h1)) * 4096.0f,
                                   (x.w - __high2float(h1)) * 4096.0f);
    uint2 hv; hv.x = *(uint32_t*)&h0; hv.y = *(uint32_t*)&h1;
    uint2 lv; lv.x = *(uint32_t*)&l0; lv.y = *(uint32_t*)&l1;
    ((uint2*)g_Whf)[i] = hv;
    ((uint2*)g_Wlf)[i] = lv;
}

// ---------------- kernel B: q + v GEMVs, split-K x8 (warp per partial) --
__global__ __launch_bounds__(256) void qv_kernel(
    const float* __restrict__ hidden,
    const float* __restrict__ Wq, const float* __restrict__ Wr)
{
    int gw = blockIdx.x * 8 + (threadIdx.x >> 5);   // 0..16383
    int lane = threadIdx.x & 31;
    int sp   = gw & (QSPL - 1);
    int task = gw >> 3;                 // 0..2047
    const float4* x4;
    const float4* w4;
    if (task < BATCH * DDIM) {          // q task
        int b = task >> 7, d = task & 127;
        int row = g_idx[b * NSENT + NSENT - 1];
        x4 = (const float4*)(hidden + ((size_t)b * SEQ + row) * HDIM + sp * QSEG);
        w4 = (const float4*)(Wq + (size_t)d * HDIM + sp * QSEG);
    } else {                            // v task
        int tt = task - BATCH * DDIM;
        int b = tt >> 7, i = tt & 127;
        int row = g_idx[b * NSENT + i];
        x4 = (const float4*)(hidden + ((size_t)b * SEQ + row) * HDIM + sp * QSEG);
        w4 = (const float4*)(Wr + sp * QSEG);
    }
    float4 xa[4], wa[4];
#pragma unroll
    for (int it = 0; it < 4; it++) {    // all 8 LDG.128 in flight
        xa[it] = x4[it * 32 + lane];
        wa[it] = w4[it * 32 + lane];
    }
    float s = 0.f;
#pragma unroll
    for (int it = 0; it < 4; it++)
        s += xa[it].x * wa[it].x + xa[it].y * wa[it].y
           + xa[it].z * wa[it].z + xa[it].w * wa[it].w;
#pragma unroll
    for (int o = 16; o > 0; o >>= 1) s += __shfl_xor_sync(0xffffffffu, s, o);
    if (lane == 0) {
        if (task < BATCH * DDIM) g_qpart[sp * (BATCH * DDIM) + task] = s;
        else g_vpart[sp * (BATCH * NSENT) + task - BATCH * DDIM] = s;
    }
}

// ---------------- kernel C: K projection, fp16 2-term WMMA ---------------
// grid (KS2, 2*BATCH), 256 threads = 8 warps, CTA tile M=64 x N=128,
// warp tile 32x32. A fp16 tiles (hi only) for ALL 4 k-stages resident in
// smem; 8 mma-stages: j=0..3 accumulate Ah*Wlf, scale acc by 2^-12, then
// j=4..7 accumulate Ah*Whf into the same acc. W triple-buffered cp.async
// with 2-stage lead. 2 CTAs/SM, ~90 regs.
__global__ void __launch_bounds__(MMA_THREADS, 2)
mma_kernel(const float* __restrict__ hidden)
{
    extern __shared__ char smem[];
    __shared__ int idx_sh[MROWS];

    int t  = threadIdx.x;
    int sp = blockIdx.x;
    int b  = blockIdx.y >> 1, mh = blockIdx.y & 1;
    int wid = t >> 5;
    int warp_m = wid & 1;      // 0..1 -> m base = warp_m*32
    int warp_n = wid >> 1;     // 0..3 -> n base = warp_n*32

    const int k0 = sp * KSL;
    if (t < MROWS) idx_sh[t] = g_idx[b * NSENT + mh * MROWS + t];
    __syncthreads();

    // per-thread A chunk addressing: 1024 float4 chunks / 256 threads = 4
    const float* aptr[4];
    int soff[4];
#pragma unroll
    for (int i = 0; i < 4; i++) {
        int lin = t + MMA_THREADS * i;
        int row = lin >> 4, c4 = lin & 15;
        aptr[i] = hidden + ((size_t)b * SEQ + idx_sh[row]) * HDIM + c4 * 4;
        soff[i] = row * TSTRIDE + c4 * 4;     // fp16 element offset in tile
    }

    auto issueW = [&](int j) {            // j = mma-stage 0..7
        const __half* warr = (j < NSTG) ? g_Wlf : g_Whf;
        int kk = k0 + (j & 3) * STG;
        char* wt = smem + A_TOTAL + (j % WBUFS) * WTILE_H;
#pragma unroll
        for (int i = 0; i < 4; i++) {     // 1024 16B chunks (128 rows x 8)
            int lin = t + MMA_THREADS * i;
            int row = lin >> 3, ch = lin & 7;
            cp_async16(smem_u32(wt + row * (TSTRIDE * 2) + ch * 16),
                       warr + (size_t)row * HDIM + kk + ch * 8);
        }
        CP_COMMIT();
    };
    auto loadA = [&](int s, float4* r) {
        int kk = k0 + s * STG;
#pragma unroll
        for (int i = 0; i < 4; i++) r[i] = *(const float4*)(aptr[i] + kk);
    };
    auto convertA = [&](int s, const float4* r) {   // fp32 regs -> fp16 tile s
        __half* At = (__half*)(smem + s * ATILE_H);
#pragma unroll
        for (int i = 0; i < 4; i++) {
            __half2 h01 = __floats2half2_rn(r[i].x, r[i].y);
            __half2 h23 = __floats2half2_rn(r[i].z, r[i].w);
            uint2 hv; hv.x = *(uint32_t*)&h01; hv.y = *(uint32_t*)&h23;
            *(uint2*)(At + soff[i]) = hv;
        }
    };

    wmma::fragment<wmma::accumulator, 16, 16, 16, float> acc[2][2];
#pragma unroll
    for (int i = 0; i < 2; i++)
#pragma unroll
        for (int j = 0; j < 2; j++) wmma::fill_fragment(acc[i][j], 0.0f);

    // prologue: W0..W2 in flight; gather+convert all 4 A stages (2-deep)
    issueW(0); issueW(1); issueW(2);
    {
        float4 ra[4], rb[4];
        loadA(0, ra); loadA(1, rb);
        convertA(0, ra); loadA(2, ra);
        convertA(1, rb); loadA(3, rb);
        convertA(2, ra);
        convertA(3, rb);
    }
    __syncthreads();     // A tiles visible to all warps

#pragma unroll
    for (int j = 0; j < 2 * NSTG; j++) {
        if (j < 6)      { CP_WAIT(2); }   // W(j) complete
        else if (j == 6){ CP_WAIT(1); }
        else            { CP_WAIT(0); }
        __syncthreads();                  // W(j) visible CTA-wide

        const __half* At = (const __half*)(smem + (j & 3) * ATILE_H);
        const __half* Wt = (const __half*)(smem + A_TOTAL + (j % WBUFS) * WTILE_H);
        const __half* Ab = At + warp_m * 32 * TSTRIDE;
        const __half* Wb = Wt + warp_n * 32 * TSTRIDE;

#pragma unroll
        for (int kk = 0; kk < STG / 16; kk++) {
            wmma::fragment<wmma::matrix_a, 16, 16, 16, __half, wmma::row_major> ah[2];
            wmma::fragment<wmma::matrix_b, 16, 16, 16, __half, wmma::col_major> wf[2];
#pragma unroll
            for (int i = 0; i < 2; i++)
                wmma::load_matrix_sync(ah[i], Ab + i * 16 * TSTRIDE + kk * 16, TSTRIDE);
#pragma unroll
            for (int jn = 0; jn < 2; jn++)
                wmma::load_matrix_sync(wf[jn], Wb + jn * 16 * TSTRIDE + kk * 16, TSTRIDE);
#pragma unroll
            for (int i = 0; i < 2; i++)
#pragma unroll
                for (int jn = 0; jn < 2; jn++)
                    wmma::mma_sync(acc[i][jn], ah[i], wf[jn], acc[i][jn]);
        }

        if (j == NSTG - 1) {              // Wl pass done: undo the 2^12 scale
#pragma unroll
            for (int i = 0; i < 2; i++)
#pragma unroll
                for (int jn = 0; jn < 2; jn++)
#pragma unroll
                    for (int e = 0; e < acc[i][jn].num_elements; e++)
                        acc[i][jn].x[e] *= 0.000244140625f;   // 2^-12
        }

        __syncthreads();                  // all warps done reading W buf
        if (j + WBUFS < 2 * NSTG) issueW(j + WBUFS);
    }

    // ---- epilogue: store split-K partial (this CTA's 64-row half) ----
    float* out = g_part + (((size_t)(sp * BATCH + b)) << 14) + (size_t)mh * MROWS * DDIM;
#pragma unroll
    for (int i = 0; i < 2; i++)
#pragma unroll
        for (int jn = 0; jn < 2; jn++)
            wmma::store_matrix_sync(out + (size_t)(warp_m * 32 + i * 16) * DDIM
                                        + warp_n * 32 + jn * 16,
                                    acc[i][jn], DDIM, wmma::mem_row_major);
}

// ---------------- kernel D: split-K reduce + bias + RoPE (float2) ----
__global__ __launch_bounds__(256) void kred_kernel(const float* __restrict__ bk) {
    int p = blockIdx.x * 256 + threadIdx.x;       // pair id over B*NS*64 = 65536
    if (p >= BATCH * NSENT * 64) return;
    int b = p >> 13;
    int t = (p >> 6) & 127;                        // sentence index
    int j = p & 63;                                // rotation pair
    int off2 = p & 8191;                           // (t*64 + j)
    float2 s = ((const float2*)bk)[j];
#pragma unroll
    for (int sp = 0; sp < KS2; sp++) {
        float2 v = ((const float2*)g_part)[(((size_t)(sp * BATCH + b)) << 13) + off2];
        s.x += v.x; s.y += v.y;
    }
    // RoPE at position t:  f = theta^(-j/64) = exp2(-j * log2(1e4)/64)
    float f = exp2f(-(float)j * 0.20762050593045163f);
    float ang = (float)t * f;
    float sn, cs; sincosf(ang, &sn, &cs);
    float2 o;
    o.x = s.x * cs - s.y * sn;
    o.y = s.x * sn + s.y * cs;
    ((float2*)g_kf)[p] = o;
}

// ---------------- kernel E: attention + rewards ----------------------
__global__ __launch_bounds__(128) void finalize_kernel(float* __restrict__ out,
                                                       const float* __restrict__ bq,
                                                       const float* __restrict__ br) {
    __shared__ float qfull[DDIM];
    __shared__ float qsh[DDIM];
    __shared__ float red[NSENT];
    __shared__ float vsh[NSENT];
    int b = blockIdx.x, t = threadIdx.x;

    const double LN1E4   = 9.210340371976184;      // ln(10000)
    const double INV_2PI = 0.15915494309189535;
    const double TWO_PI  = 6.283185307179586;

    // reduce v partials (deterministic order) + bias
    {
        float v = br[0];
#pragma unroll
        for (int sp = 0; sp < QSPL; sp++)
            v += g_vpart[sp * (BATCH * NSENT) + b * NSENT + t];
        vsh[t] = v;
    }
    // reduce q partials (deterministic order) + bias
    {
        float qv = bq[t];
#pragma unroll
        for (int sp = 0; sp < QSPL; sp++)
            qv += g_qpart[sp * (BATCH * DDIM) + b * DDIM + t];
        qfull[t] = qv;
    }
    __syncthreads();

    // RoPE q at position NSENT-1, pre-scaled by 1/sqrt(D)
    if (t < DDIM / 2) {
        double f   = exp(-((double)(2 * t) / (double)DDIM) * LN1E4);
        double ang = (double)(NSENT - 1) * f;
        double kk  = rint(ang * INV_2PI);
        float  ar  = (float)(ang - kk * TWO_PI);
        float c, sn; sincosf(ar, &sn, &c);
        float re = qfull[2 * t], im = qfull[2 * t + 1];
        const float isd = 0.08838834764831845f;    // 1/sqrt(128)
        qsh[2 * t]     = (re * c - im * sn) * isd;
        qsh[2 * t + 1] = (re * sn + im * c) * isd;
    }
    __syncthreads();

    // logit_t = rope(k_t) . rope(q)/sqrt(D)  (k already rotated in kred)
    const float4* krow = (const float4*)(g_kf + ((size_t)b << 14) + (size_t)t * DDIM);
    const float4* q4   = (const float4*)qsh;
    float logit = 0.f;
#pragma unroll
    for (int j = 0; j < DDIM / 4; j++) {
        float4 k4 = krow[j], qq = q4[j];
        logit += k4.x * qq.x + k4.y * qq.y + k4.z * qq.z + k4.w * qq.w;
    }

    // softmax over the 128 sentences
    red[t] = logit; __syncthreads();
#pragma unroll
    for (int o = 64; o > 0; o >>= 1) { if (t < o) red[t] = fmaxf(red[t], red[t + o]); __syncthreads(); }
    float mx = red[0]; __syncthreads();
    float e = expf(logit - mx);
    red[t] = e; __syncthreads();
#pragma unroll
    for (int o = 64; o > 0; o >>= 1) { if (t < o) red[t] += red[t + o]; __syncthreads(); }
    float ssum = red[0]; __syncthreads();
    float attn = e / ssum;

    float v  = vsh[t];
    float sr = (t == 0) ? v : (v - vsh[t - 1]);
    float srw = sr * attn;
    out[b * NSENT + t] = srw;

    red[t] = srw; __syncthreads();
#pragma unroll
    for (int o = 64; o > 0; o >>= 1) { if (t < o) red[t] += red[t + o]; __syncthreads(); }
    if (t == 0) out[BATCH * NSENT + b] = red[0];
}

// ---------------- host launcher (5 graph nodes, qv forked) ----------
extern "C" void kernel_launch(void* const* d_in, const int* in_sizes, int n_in,
                              void* d_out, int out_size) {
    const float* hidden = (const float*)d_in[0];
    const int*   mask   = (const int*)d_in[1];
    int off = (n_in > 2 && in_sizes[2] == 1) ? 3 : 2;
    const float* Wq = (const float*)d_in[off + 0];
    const float* bq = (const float*)d_in[off + 1];
    const float* Wk = (const float*)d_in[off + 2];
    const float* bk = (const float*)d_in[off + 3];
    const float* Wr = (const float*)d_in[off + 4];
    const float* br = (const float*)d_in[off + 5];
    float* out = (float*)d_out;

    cudaFuncSetAttribute(mma_kernel, cudaFuncAttributeMaxDynamicSharedMemorySize,
                         MMA_SMEM_TOTAL);

    // side stream for qv (created per-call; only correctness/capture calls run
    // host code — replays are graph-only; intentionally leaked, see R13 note)
    cudaStream_t side = 0;
    cudaEvent_t e1 = 0, e2 = 0;
    bool forked = (cudaStreamCreateWithFlags(&side, cudaStreamNonBlocking) == cudaSuccess);
    if (forked) forked = (cudaEventCreateWithFlags(&e1, cudaEventDisableTiming) == cudaSuccess);
    if (forked) forked = (cudaEventCreateWithFlags(&e2, cudaEventDisableTiming) == cudaSuccess);

    // node 1: fused idx + W pre-split
    prep_kernel<<<BATCH + DDIM * HDIM / 4 / 256, 256>>>(mask, Wk);
    if (forked) {
        cudaEventRecord(e1, 0);
        cudaStreamWaitEvent(side, e1, 0);
        qv_kernel<<<QSPL * 2 * BATCH * NSENT / 8, 256, 0, side>>>(hidden, Wq, Wr);
        cudaEventRecord(e2, side);
    } else {
        qv_kernel<<<QSPL * 2 * BATCH * NSENT / 8, 256>>>(hidden, Wq, Wr);
    }
    mma_kernel<<<dim3(KS2, 2 * BATCH), MMA_THREADS, MMA_SMEM_TOTAL>>>(hidden);
    kred_kernel<<<(BATCH * NSENT * 64 + 255) / 256, 256>>>(bk);
    if (forked) cudaStreamWaitEvent(0, e2, 0);
    finalize_kernel<<<BATCH, 128>>>(out, bq, br);
    (void)in_sizes; (void)n_in; (void)out_size;
}

// round 16
// speedup vs baseline: 1.4588x; 1.1576x over previous
#include <cuda_runtime.h>
#include <cuda_bf16.h>
#include <cuda_fp16.h>
#include <mma.h>
#include <math.h>
#include <cstdint>

using namespace nvcuda;

// Problem constants (fixed by the dataset)
#define BATCH 8
#define SEQ   2048
#define HDIM  4096
#define DDIM  128
#define NSENT 128

// split-K for the HMMA GEMM
#define KS2   16
#define KSL   (HDIM / KS2)     // 256 fp32 k per CTA
#define STG   64               // k per stage
#define NSTG  (KSL / KS2 * 4 / 4)  // placeholder (see below)
#undef NSTG
#define NSTG  (KSL / STG)      // 4 mma-stages (single fp16 term)
#define MMA_THREADS 256        // 8 warps; CTA tile M=64 x N=128
#define MROWS 64               // sentence rows per CTA (M-split x2)

// split-K for the q/v GEMVs
#define QSPL  8
#define QSEG  (HDIM / QSPL)    // 512 floats per warp segment

#define TSTRIDE 72                       // fp16 tile row stride (144B)
#define ATILE_H (MROWS * TSTRIDE * 2)    // 9216 B per A fp16 stage tile
#define A_TOTAL (NSTG * ATILE_H)         // 36864 B (all 4 stages resident)
#define WTILE_H (128 * TSTRIDE * 2)      // 18432 B per W fp16 stage tile
#define WBUFS   3
#define MMA_SMEM_TOTAL (A_TOTAL + WBUFS * WTILE_H)   // 92160 B -> 2 CTAs/SM

// ---------------- scratch (no allocations allowed) ----------------
__device__ int   g_idx[BATCH * NSENT];
__device__ float g_qpart[QSPL * BATCH * DDIM];               // 32 KB
__device__ float g_vpart[QSPL * BATCH * NSENT];              // 32 KB
__device__ float g_part[(size_t)KS2 * BATCH * NSENT * DDIM]; // 8 MB fp32 partials
__device__ float g_kf [(size_t)BATCH * NSENT * DDIM];        // 512 KB (RoPE'd K)
__device__ __half g_Whf[(size_t)DDIM * HDIM];                // 1 MB  fp16(W)

// ---------------- PTX helpers (baseline compute_103 only!) ----------------
__device__ __forceinline__ uint32_t smem_u32(const void* p) {
    uint32_t a;
    asm("{ .reg .u64 t; cvta.to.shared.u64 t, %1; cvt.u32.u64 %0, t; }" : "=r"(a) : "l"(p));
    return a;
}
__device__ __forceinline__ void cp_async16(uint32_t saddr, const void* g) {
    asm volatile("cp.async.cg.shared.global [%0], [%1], 16;" :: "r"(saddr), "l"(g));
}
#define CP_COMMIT() asm volatile("cp.async.commit_group;" ::: "memory")
#define CP_WAIT(n)  asm volatile("cp.async.wait_group %0;" :: "n"(n) : "memory")

// ---------------- kernel A: fused idx (blocks 0-7) + W fp16 convert ------
__global__ __launch_bounds__(256) void prep_kernel(const int* __restrict__ mask,
                                                   const float* __restrict__ Wk) {
    if (blockIdx.x < BATCH) {
        // sentence-position extraction, MLP-64, warp 0 only
        if (threadIdx.x >= 32) return;
        int b = blockIdx.x;
        int lane = threadIdx.x;
        const int4* row = (const int4*)(mask + (size_t)b * SEQ);
        int4 v[16];
#pragma unroll
        for (int i = 0; i < 16; i++) v[i] = row[i * 32 + lane];
        unsigned lt = (1u << lane) - 1u;
        int count = 0;
#pragma unroll
        for (int i = 0; i < 16; i++) {
            unsigned b0 = __ballot_sync(0xffffffffu, v[i].x != 0);
            unsigned b1 = __ballot_sync(0xffffffffu, v[i].y != 0);
            unsigned b2 = __ballot_sync(0xffffffffu, v[i].z != 0);
            unsigned b3 = __ballot_sync(0xffffffffu, v[i].w != 0);
            int prel = __popc(b0 & lt) + __popc(b1 & lt) + __popc(b2 & lt) + __popc(b3 & lt);
            int basepos = i * 128 + lane * 4;
            int slot = count + prel;
            if (v[i].x) { if (slot < NSENT) g_idx[b * NSENT + slot] = basepos + 0; slot++; }
            if (v[i].y) { if (slot < NSENT) g_idx[b * NSENT + slot] = basepos + 1; slot++; }
            if (v[i].z) { if (slot < NSENT) g_idx[b * NSENT + slot] = basepos + 2; slot++; }
            if (v[i].w) { if (slot < NSENT) g_idx[b * NSENT + slot] = basepos + 3; slot++; }
            count += __popc(b0) + __popc(b1) + __popc(b2) + __popc(b3);
        }
        return;
    }
    // W fp16 convert
    int i = (blockIdx.x - BATCH) * 256 + threadIdx.x;   // over DDIM*HDIM/4
    if (i >= DDIM * HDIM / 4) return;
    float4 x = ((const float4*)Wk)[i];
    __half2 h0 = __floats2half2_rn(x.x, x.y);
    __half2 h1 = __floats2half2_rn(x.z, x.w);
    uint2 hv; hv.x = *(uint32_t*)&h0; hv.y = *(uint32_t*)&h1;
    ((uint2*)g_Whf)[i] = hv;
}

// ---------------- kernel B: q + v GEMVs, split-K x8 (warp per partial) --
__global__ __launch_bounds__(256) void qv_kernel(
    const float* __restrict__ hidden,
    const float* __restrict__ Wq, const float* __restrict__ Wr)
{
    int gw = blockIdx.x * 8 + (threadIdx.x >> 5);   // 0..16383
    int lane = threadIdx.x & 31;
    int sp   = gw & (QSPL - 1);
    int task = gw >> 3;                 // 0..2047
    const float4* x4;
    const float4* w4;
    if (task < BATCH * DDIM) {          // q task
        int b = task >> 7, d = task & 127;
        int row = g_idx[b * NSENT + NSENT - 1];
        x4 = (const float4*)(hidden + ((size_t)b * SEQ + row) * HDIM + sp * QSEG);
        w4 = (const float4*)(Wq + (size_t)d * HDIM + sp * QSEG);
    } else {                            // v task
        int tt = task - BATCH * DDIM;
        int b = tt >> 7, i = tt & 127;
        int row = g_idx[b * NSENT + i];
        x4 = (const float4*)(hidden + ((size_t)b * SEQ + row) * HDIM + sp * QSEG);
        w4 = (const float4*)(Wr + sp * QSEG);
    }
    float4 xa[4], wa[4];
#pragma unroll
    for (int it = 0; it < 4; it++) {    // all 8 LDG.128 in flight
        xa[it] = x4[it * 32 + lane];
        wa[it] = w4[it * 32 + lane];
    }
    float s = 0.f;
#pragma unroll
    for (int it = 0; it < 4; it++)
        s += xa[it].x * wa[it].x + xa[it].y * wa[it].y
           + xa[it].z * wa[it].z + xa[it].w * wa[it].w;
#pragma unroll
    for (int o = 16; o > 0; o >>= 1) s += __shfl_xor_sync(0xffffffffu, s, o);
    if (lane == 0) {
        if (task < BATCH * DDIM) g_qpart[sp * (BATCH * DDIM) + task] = s;
        else g_vpart[sp * (BATCH * NSENT) + task - BATCH * DDIM] = s;
    }
}

// ---------------- kernel C: K projection, single-term fp16 WMMA ----------
// grid (KS2, 2*BATCH), 256 threads = 8 warps, CTA tile M=64 x N=128,
// warp tile 32x32. A fp16 tiles for all 4 k-stages resident in smem;
// W triple-buffered cp.async with 2-stage lead. 2 CTAs/SM.
__global__ void __launch_bounds__(MMA_THREADS, 2)
mma_kernel(const float* __restrict__ hidden)
{
    extern __shared__ char smem[];
    __shared__ int idx_sh[MROWS];

    int t  = threadIdx.x;
    int sp = blockIdx.x;
    int b  = blockIdx.y >> 1, mh = blockIdx.y & 1;
    int wid = t >> 5;
    int warp_m = wid & 1;      // 0..1 -> m base = warp_m*32
    int warp_n = wid >> 1;     // 0..3 -> n base = warp_n*32

    const int k0 = sp * KSL;
    if (t < MROWS) idx_sh[t] = g_idx[b * NSENT + mh * MROWS + t];
    __syncthreads();

    // per-thread A chunk addressing: 1024 float4 chunks / 256 threads = 4
    const float* aptr[4];
    int soff[4];
#pragma unroll
    for (int i = 0; i < 4; i++) {
        int lin = t + MMA_THREADS * i;
        int row = lin >> 4, c4 = lin & 15;
        aptr[i] = hidden + ((size_t)b * SEQ + idx_sh[row]) * HDIM + c4 * 4;
        soff[i] = row * TSTRIDE + c4 * 4;     // fp16 element offset in tile
    }

    auto issueW = [&](int j) {            // j = mma-stage 0..3
        int kk = k0 + j * STG;
        char* wt = smem + A_TOTAL + (j % WBUFS) * WTILE_H;
#pragma unroll
        for (int i = 0; i < 4; i++) {     // 1024 16B chunks (128 rows x 8)
            int lin = t + MMA_THREADS * i;
            int row = lin >> 3, ch = lin & 7;
            cp_async16(smem_u32(wt + row * (TSTRIDE * 2) + ch * 16),
                       g_Whf + (size_t)row * HDIM + kk + ch * 8);
        }
        CP_COMMIT();
    };
    auto loadA = [&](int s, float4* r) {
        int kk = k0 + s * STG;
#pragma unroll
        for (int i = 0; i < 4; i++) r[i] = *(const float4*)(aptr[i] + kk);
    };
    auto convertA = [&](int s, const float4* r) {   // fp32 regs -> fp16 tile s
        __half* At = (__half*)(smem + s * ATILE_H);
#pragma unroll
        for (int i = 0; i < 4; i++) {
            __half2 h01 = __floats2half2_rn(r[i].x, r[i].y);
            __half2 h23 = __floats2half2_rn(r[i].z, r[i].w);
            uint2 hv; hv.x = *(uint32_t*)&h01; hv.y = *(uint32_t*)&h23;
            *(uint2*)(At + soff[i]) = hv;
        }
    };

    wmma::fragment<wmma::accumulator, 16, 16, 16, float> acc[2][2];
#pragma unroll
    for (int i = 0; i < 2; i++)
#pragma unroll
        for (int j = 0; j < 2; j++) wmma::fill_fragment(acc[i][j], 0.0f);

    // prologue: W0..W2 in flight; gather+convert all 4 A stages (2-deep)
    issueW(0); issueW(1); issueW(2);
    {
        float4 ra[4], rb[4];
        loadA(0, ra); loadA(1, rb);
        convertA(0, ra); loadA(2, ra);
        convertA(1, rb); loadA(3, rb);
        convertA(2, ra);
        convertA(3, rb);
    }
    __syncthreads();     // A tiles visible to all warps

#pragma unroll
    for (int j = 0; j < NSTG; j++) {
        if (j <= 1)      { CP_WAIT(2); }   // W(j) complete
        else if (j == 2) { CP_WAIT(1); }
        else             { CP_WAIT(0); }
        __syncthreads();                   // W(j) visible CTA-wide

        const __half* At = (const __half*)(smem + j * ATILE_H);
        const __half* Wt = (const __half*)(smem + A_TOTAL + (j % WBUFS) * WTILE_H);
        const __half* Ab = At + warp_m * 32 * TSTRIDE;
        const __half* Wb = Wt + warp_n * 32 * TSTRIDE;

#pragma unroll
        for (int kk = 0; kk < STG / 16; kk++) {
            wmma::fragment<wmma::matrix_a, 16, 16, 16, __half, wmma::row_major> ah[2];
            wmma::fragment<wmma::matrix_b, 16, 16, 16, __half, wmma::col_major> wf[2];
#pragma unroll
            for (int i = 0; i < 2; i++)
                wmma::load_matrix_sync(ah[i], Ab + i * 16 * TSTRIDE + kk * 16, TSTRIDE);
#pragma unroll
            for (int jn = 0; jn < 2; jn++)
                wmma::load_matrix_sync(wf[jn], Wb + jn * 16 * TSTRIDE + kk * 16, TSTRIDE);
#pragma unroll
            for (int i = 0; i < 2; i++)
#pragma unroll
                for (int jn = 0; jn < 2; jn++)
                    wmma::mma_sync(acc[i][jn], ah[i], wf[jn], acc[i][jn]);
        }

        __syncthreads();                  // all warps done reading W buf
        if (j + WBUFS < NSTG) issueW(j + WBUFS);
    }

    // ---- epilogue: store split-K partial (this CTA's 64-row half) ----
    float* out = g_part + (((size_t)(sp * BATCH + b)) << 14) + (size_t)mh * MROWS * DDIM;
#pragma unroll
    for (int i = 0; i < 2; i++)
#pragma unroll
        for (int jn = 0; jn < 2; jn++)
            wmma::store_matrix_sync(out + (size_t)(warp_m * 32 + i * 16) * DDIM
                                        + warp_n * 32 + jn * 16,
                                    acc[i][jn], DDIM, wmma::mem_row_major);
}

// ---------------- kernel D: split-K reduce + bias + RoPE (float4) ----
// one thread per QUAD (2 rotation pairs): 16 LDG.128 in flight per thread.
__global__ __launch_bounds__(256) void kred_kernel(const float* __restrict__ bk) {
    int p = blockIdx.x * 256 + threadIdx.x;       // quad id over B*NS*32 = 32768
    if (p >= BATCH * NSENT * 32) return;
    int b  = p >> 12;                              // 4096 quads per batch
    int t  = (p >> 5) & 127;                       // sentence index
    int jq = p & 31;                               // quad: pairs 2jq, 2jq+1
    int off4 = p & 4095;                           // float4 index within batch
    float4 s = ((const float4*)bk)[jq];
#pragma unroll
    for (int sp = 0; sp < KS2; sp++) {
        float4 v = ((const float4*)g_part)[(((size_t)(sp * BATCH + b)) << 12) + off4];
        s.x += v.x; s.y += v.y; s.z += v.z; s.w += v.w;
    }
    // RoPE at position t for pairs j0=2jq, j1=2jq+1
    const float c = 0.20762050593045163f;          // log2(1e4)/64
    float f0 = exp2f(-(float)(2 * jq) * c);
    float f1 = exp2f(-(float)(2 * jq + 1) * c);
    float sn0, cs0, sn1, cs1;
    sincosf((float)t * f0, &sn0, &cs0);
    sincosf((float)t * f1, &sn1, &cs1);
    float4 o;
    o.x = s.x * cs0 - s.y * sn0;
    o.y = s.x * sn0 + s.y * cs0;
    o.z = s.z * cs1 - s.w * sn1;
    o.w = s.z * sn1 + s.w * cs1;
    ((float4*)g_kf)[p] = o;
}

// ---------------- kernel E: attention + rewards ----------------------
__global__ __launch_bounds__(128) void finalize_kernel(float* __restrict__ out,
                                                       const float* __restrict__ bq,
                                                       const float* __restrict__ br) {
    __shared__ float qfull[DDIM];
    __shared__ float qsh[DDIM];
    __shared__ float red[NSENT];
    __shared__ float vsh[NSENT];
    int b = blockIdx.x, t = threadIdx.x;

    const double LN1E4   = 9.210340371976184;      // ln(10000)
    const double INV_2PI = 0.15915494309189535;
    const double TWO_PI  = 6.283185307179586;

    // reduce v partials (deterministic order) + bias
    {
        float v = br[0];
#pragma unroll
        for (int sp = 0; sp < QSPL; sp++)
            v += g_vpart[sp * (BATCH * NSENT) + b * NSENT + t];
        vsh[t] = v;
    }
    // reduce q partials (deterministic order) + bias
    {
        float qv = bq[t];
#pragma unroll
        for (int sp = 0; sp < QSPL; sp++)
            qv += g_qpart[sp * (BATCH * DDIM) + b * DDIM + t];
        qfull[t] = qv;
    }
    __syncthreads();

    // RoPE q at position NSENT-1, pre-scaled by 1/sqrt(D)
    if (t < DDIM / 2) {
        double f   = exp(-((double)(2 * t) / (double)DDIM) * LN1E4);
        double ang = (double)(NSENT - 1) * f;
        double kk  = rint(ang * INV_2PI);
        float  ar  = (float)(ang - kk * TWO_PI);
        float c, sn; sincosf(ar, &sn, &c);
        float re = qfull[2 * t], im = qfull[2 * t + 1];
        const float isd = 0.08838834764831845f;    // 1/sqrt(128)
        qsh[2 * t]     = (re * c - im * sn) * isd;
        qsh[2 * t + 1] = (re * sn + im * c) * isd;
    }
    __syncthreads();

    // logit_t = rope(k_t) . rope(q)/sqrt(D)  (k already rotated in kred)
    const float4* krow = (const float4*)(g_kf + ((size_t)b << 14) + (size_t)t * DDIM);
    const float4* q4   = (const float4*)qsh;
    float logit = 0.f;
#pragma unroll
    for (int j = 0; j < DDIM / 4; j++) {
        float4 k4 = krow[j], qq = q4[j];
        logit += k4.x * qq.x + k4.y * qq.y + k4.z * qq.z + k4.w * qq.w;
    }

    // softmax over the 128 sentences
    red[t] = logit; __syncthreads();
#pragma unroll
    for (int o = 64; o > 0; o >>= 1) { if (t < o) red[t] = fmaxf(red[t], red[t + o]); __syncthreads(); }
    float mx = red[0]; __syncthreads();
    float e = expf(logit - mx);
    red[t] = e; __syncthreads();
#pragma unroll
    for (int o = 64; o > 0; o >>= 1) { if (t < o) red[t] += red[t + o]; __syncthreads(); }
    float ssum = red[0]; __syncthreads();
    float attn = e / ssum;

    float v  = vsh[t];
    float sr = (t == 0) ? v : (v - vsh[t - 1]);
    float srw = sr * attn;
    out[b * NSENT + t] = srw;

    red[t] = srw; __syncthreads();
#pragma unroll
    for (int o = 64; o > 0; o >>= 1) { if (t < o) red[t] += red[t + o]; __syncthreads(); }
    if (t == 0) out[BATCH * NSENT + b] = red[0];
}

// ---------------- host launcher (5 graph nodes, qv forked) ----------
extern "C" void kernel_launch(void* const* d_in, const int* in_sizes, int n_in,
                              void* d_out, int out_size) {
    const float* hidden = (const float*)d_in[0];
    const int*   mask   = (const int*)d_in[1];
    int off = (n_in > 2 && in_sizes[2] == 1) ? 3 : 2;
    const float* Wq = (const float*)d_in[off + 0];
    const float* bq = (const float*)d_in[off + 1];
    const float* Wk = (const float*)d_in[off + 2];
    const float* bk = (const float*)d_in[off + 3];
    const float* Wr = (const float*)d_in[off + 4];
    const float* br = (const float*)d_in[off + 5];
    float* out = (float*)d_out;

    cudaFuncSetAttribute(mma_kernel, cudaFuncAttributeMaxDynamicSharedMemorySize,
                         MMA_SMEM_TOTAL);

    // side stream for qv (created per-call; only correctness/capture calls run
    // host code — replays are graph-only; intentionally leaked, see R13 note)
    cudaStream_t side = 0;
    cudaEvent_t e1 = 0, e2 = 0;
    bool forked = (cudaStreamCreateWithFlags(&side, cudaStreamNonBlocking) == cudaSuccess);
    if (forked) forked = (cudaEventCreateWithFlags(&e1, cudaEventDisableTiming) == cudaSuccess);
    if (forked) forked = (cudaEventCreateWithFlags(&e2, cudaEventDisableTiming) == cudaSuccess);

    // node 1: fused idx + W fp16 convert
    prep_kernel<<<BATCH + DDIM * HDIM / 4 / 256, 256>>>(mask, Wk);
    if (forked) {
        cudaEventRecord(e1, 0);
        cudaStreamWaitEvent(side, e1, 0);
        qv_kernel<<<QSPL * 2 * BATCH * NSENT / 8, 256, 0, side>>>(hidden, Wq, Wr);
        cudaEventRecord(e2, side);
    } else {
        qv_kernel<<<QSPL * 2 * BATCH * NSENT / 8, 256>>>(hidden, Wq, Wr);
    }
    mma_kernel<<<dim3(KS2, 2 * BATCH), MMA_THREADS, MMA_SMEM_TOTAL>>>(hidden);
    kred_kernel<<<(BATCH * NSENT * 32 + 255) / 256, 256>>>(bk);
    if (forked) cudaStreamWaitEvent(0, e2, 0);
    finalize_kernel<<<BATCH, 128>>>(out, bq, br);
    (void)in_sizes; (void)n_in; (void)out_size;
}